// round 5
// baseline (speedup 1.0000x reference)
#include <cuda_runtime.h>
#include <math.h>

#define BB 16
#define CC 384
#define HH 96
#define WW 96
#define HW (HH*WW)
#define CAND 2048
#define ANCH 512
#define KK2 49
#define TAU_INV 10.0f

// ---------------- scratch (device globals; no allocation anywhere) ----------------
__device__ float g_tn[(size_t)BB*HW*CC];      // teacher, normalized, channels-last [b][y][x][c]
__device__ float g_sn[(size_t)BB*HW*CC];      // student,  normalized, channels-last
__device__ float g_sims[(size_t)BB*CAND*KK2]; // teacher sims (already /TAU)
__device__ float g_ent[BB*CAND];
__device__ int   g_sel[BB*ANCH];
__device__ float g_loss;

// pixel offsets dy*WW+dx for window index o (row-major 7x7), padded to 52 with clamps
__constant__ int c_doff[52] = {
 -291,-290,-289,-288,-287,-286,-285,
 -195,-194,-193,-192,-191,-190,-189,
  -99, -98, -97, -96, -95, -94, -93,
   -3,  -2,  -1,   0,   1,   2,   3,
   93,  94,  95,  96,  97,  98,  99,
  189, 190, 191, 192, 193, 194, 195,
  285, 286, 287, 288, 289, 290, 291,
  291, 291, 291 };

// ---------------- k0: zero the loss accumulator ----------------
__global__ void k_zero() { g_loss = 0.0f; }

// ---------------- k1: fused per-pixel L2-normalize + transpose to channels-last ----
#define PIX 16
template <int DST>
__global__ void __launch_bounds__(256) k_norm_transpose(const float* __restrict__ in) {
    __shared__ float tile[CC][PIX + 1];
    __shared__ float ssum[16][PIX];
    __shared__ float rinv[PIX];
    int blk  = blockIdx.x;
    int b    = blk / (HW / PIX);
    int pix0 = (blk % (HW / PIX)) * PIX;
    int t    = threadIdx.x;
    int p    = t & (PIX - 1);
    int cr   = t >> 4;                       // 0..15
    const float* src = in + (size_t)b * CC * HW + pix0;
    float acc = 0.0f;
#pragma unroll
    for (int i = 0; i < CC / 16; i++) {      // 24 iters
        int c = i * 16 + cr;
        float v = src[(size_t)c * HW + p];
        tile[c][p] = v;
        acc += v * v;
    }
    ssum[cr][p] = acc;
    __syncthreads();
    if (cr == 0) {
        float s = 0.0f;
#pragma unroll
        for (int r = 0; r < 16; r++) s += ssum[r][p];
        rinv[p] = 1.0f / fmaxf(sqrtf(s), 1e-12f);
    }
    __syncthreads();
    int lane = t & 31, w = t >> 5;           // 8 warps
    float* gout = (DST == 0) ? g_tn : g_sn;
    float* dst = gout + ((size_t)b * HW + pix0) * CC;
#pragma unroll
    for (int j = 0; j < PIX / 8; j++) {      // 2
        int pp = w * (PIX / 8) + j;
        float r = rinv[pp];
#pragma unroll
        for (int i2 = 0; i2 < CC / 32; i2++) {  // 12, coalesced 128B stores
            int c = lane + 32 * i2;
            dst[(size_t)pp * CC + c] = tile[c][pp] * r;
        }
    }
}

// ---------------- distributed window sims ----------------
// Warp layout: lane = 8*g + l. Group g (0..3) owns offsets o = g*13+j (j=0..12,
// padded/clamped beyond 48). Lane l covers channels {l+8i}, i=0..11 (float4).
// Reduce per offset = 3-level butterfly over the 8 lanes of the group; all 4
// groups reduce concurrently in the same SHFL instruction.
// Post: s[j] = sims(o=g*13+j)/TAU, identical across the 8 lanes of a group.
__device__ __forceinline__ void window_sims13(const float* __restrict__ feat,
                                              int b, int y, int x,
                                              int g, int l, float s[13]) {
    const float4* base = (const float4*)(feat + (size_t)b * HW * CC);
    const float4* cp = base + (size_t)(y * WW + x) * (CC / 4);
    float4 c0[12];
#pragma unroll
    for (int i = 0; i < 12; i++) c0[i] = cp[l + 8 * i];
#pragma unroll
    for (int j = 0; j < 13; j++) {
        int o = g * 13 + j;
        const float4* np = cp + (ptrdiff_t)c_doff[o] * (CC / 4);
        float d = 0.0f;
#pragma unroll
        for (int i = 0; i < 12; i++) {
            float4 n = np[l + 8 * i];
            d = fmaf(c0[i].x, n.x, d);
            d = fmaf(c0[i].y, n.y, d);
            d = fmaf(c0[i].z, n.z, d);
            d = fmaf(c0[i].w, n.w, d);
        }
        d += __shfl_xor_sync(0xffffffffu, d, 1);
        d += __shfl_xor_sync(0xffffffffu, d, 2);
        d += __shfl_xor_sync(0xffffffffu, d, 4);
        s[j] = d * TAU_INV;
    }
}

// ---------------- k2: candidate sims (stored) + entropy ----------------
__global__ void __launch_bounds__(256, 3) k_cand(const int* __restrict__ anchors) {
    int gw   = (blockIdx.x * blockDim.x + threadIdx.x) >> 5;
    int lane = threadIdx.x & 31;
    if (gw >= BB * CAND) return;
    int b = gw >> 11;            // / CAND
    int m = gw & (CAND - 1);
    int y = anchors[2 * m], x = anchors[2 * m + 1];
    int g = lane >> 3, l = lane & 7;
    bool lead = (l == 0);

    float s[13];
    window_sims13(g_tn, b, y, x, g, l, s);

    // store sims row (group leaders: 4 lanes x 13 scattered floats)
    float* srow = g_sims + (size_t)gw * KK2;
    if (lead) {
#pragma unroll
        for (int j = 0; j < 13; j++) {
            int o = g * 13 + j;
            if (o < KK2) srow[o] = s[j];
        }
    }

    // distributed entropy of softmax(s)
    float mx = -1e30f;
#pragma unroll
    for (int j = 0; j < 13; j++) {
        int o = g * 13 + j;
        if (o < KK2) mx = fmaxf(mx, s[j]);
    }
#pragma unroll
    for (int off = 16; off; off >>= 1) mx = fmaxf(mx, __shfl_xor_sync(0xffffffffu, mx, off));

    float S = 0.0f;
#pragma unroll
    for (int j = 0; j < 13; j++) {
        int o = g * 13 + j;
        if (lead && o < KK2) S += __expf(s[j] - mx);
    }
#pragma unroll
    for (int off = 16; off; off >>= 1) S += __shfl_xor_sync(0xffffffffu, S, off);
    float rS = 1.0f / S;

    float tacc = 0.0f;
#pragma unroll
    for (int j = 0; j < 13; j++) {
        int o = g * 13 + j;
        if (lead && o < KK2) {
            float p = __expf(s[j] - mx) * rS;
            tacc += p * __logf(p + 1e-6f);
        }
    }
#pragma unroll
    for (int off = 16; off; off >>= 1) tacc += __shfl_xor_sync(0xffffffffu, tacc, off);

    if (lane == 0) g_ent[gw] = -tacc;
}

// ---------------- k3: exact top-512 (smallest entropy) per batch via bitonic sort --
__global__ void __launch_bounds__(1024) k_topk() {
    __shared__ float v[CAND];
    __shared__ int   idx[CAND];
    int b = blockIdx.x;
    int t = threadIdx.x;   // 1024
    v[t]          = g_ent[b * CAND + t];
    v[t + 1024]   = g_ent[b * CAND + t + 1024];
    idx[t]        = t;
    idx[t + 1024] = t + 1024;
    __syncthreads();
    for (int kk = 2; kk <= CAND; kk <<= 1) {
        for (int j = kk >> 1; j > 0; j >>= 1) {
            int i  = ((t & ~(j - 1)) << 1) | (t & (j - 1));
            int p2 = i | j;
            bool up = ((i & kk) == 0);
            float vi = v[i], vp = v[p2];
            if ((vi > vp) == up) {
                v[i] = vp; v[p2] = vi;
                int ti = idx[i]; idx[i] = idx[p2]; idx[p2] = ti;
            }
            __syncthreads();
        }
    }
    if (t < ANCH) g_sel[b * ANCH + t] = idx[t];   // ascending entropy -> smallest 512
}

// ---------------- k4: KL divergence over selected anchors ----------------
__global__ void __launch_bounds__(256, 2) k_kl(const int* __restrict__ anchors) {
    int gw   = (blockIdx.x * blockDim.x + threadIdx.x) >> 5;
    int lane = threadIdx.x & 31;
    if (gw >= BB * ANCH) return;
    int b = gw >> 9;             // / ANCH
    int m = g_sel[gw];
    int y = anchors[2 * m], x = anchors[2 * m + 1];
    int g = lane >> 3, l = lane & 7;
    bool lead = (l == 0);

    float ss[13];
    window_sims13(g_sn, b, y, x, g, l, ss);

    const float* trow = g_sims + (size_t)(b * CAND + m) * KK2;
    float st[13];
#pragma unroll
    for (int j = 0; j < 13; j++) {
        int o = g * 13 + j;
        st[j] = (o < KK2) ? trow[o] : -1e30f;   // group-broadcast loads
    }

    float mxs = -1e30f, mxt = -1e30f;
#pragma unroll
    for (int j = 0; j < 13; j++) {
        int o = g * 13 + j;
        if (o < KK2) mxs = fmaxf(mxs, ss[j]);
        mxt = fmaxf(mxt, st[j]);                // invalid slots are -1e30
    }
#pragma unroll
    for (int off = 16; off; off >>= 1) {
        mxs = fmaxf(mxs, __shfl_xor_sync(0xffffffffu, mxs, off));
        mxt = fmaxf(mxt, __shfl_xor_sync(0xffffffffu, mxt, off));
    }

    float Ss = 0.0f, St = 0.0f;
#pragma unroll
    for (int j = 0; j < 13; j++) {
        int o = g * 13 + j;
        if (lead && o < KK2) {
            Ss += __expf(ss[j] - mxs);
            St += __expf(st[j] - mxt);
        }
    }
#pragma unroll
    for (int off = 16; off; off >>= 1) {
        Ss += __shfl_xor_sync(0xffffffffu, Ss, off);
        St += __shfl_xor_sync(0xffffffffu, St, off);
    }
    float ls = __logf(Ss), lt = __logf(St);
    float rSt = 1.0f / St;

    float kacc = 0.0f;
#pragma unroll
    for (int j = 0; j < 13; j++) {
        int o = g * 13 + j;
        if (lead && o < KK2) {
            float dt = st[j] - mxt - lt;
            float ds = ss[j] - mxs - ls;
            kacc += __expf(st[j] - mxt) * (dt - ds);
        }
    }
#pragma unroll
    for (int off = 16; off; off >>= 1) kacc += __shfl_xor_sync(0xffffffffu, kacc, off);

    if (lane == 0) atomicAdd(&g_loss, kacc * rSt);
}

// ---------------- k5: finalize ----------------
__global__ void k_final(float* __restrict__ out) {
    out[0] = g_loss / (float)(BB * ANCH);
}

// ---------------- launch: kernel launches ONLY (graph-capture safe) ----------------
extern "C" void kernel_launch(void* const* d_in, const int* in_sizes, int n_in,
                              void* d_out, int out_size) {
    const float* student = (const float*)d_in[0];
    const float* teacher = (const float*)d_in[1];
    const int*   anchors = (const int*)d_in[2];
    float* out = (float*)d_out;

    k_zero<<<1, 1>>>();

    int nt_blocks = BB * HW / PIX;                  // 9216
    k_norm_transpose<0><<<nt_blocks, 256>>>(teacher);   // -> g_tn
    k_norm_transpose<1><<<nt_blocks, 256>>>(student);   // -> g_sn

    int cand_blocks = BB * CAND / 8;                // 4096 blocks, 8 warps each
    k_cand<<<cand_blocks, 256>>>(anchors);

    k_topk<<<BB, 1024>>>();

    int kl_blocks = BB * ANCH / 8;                  // 1024 blocks
    k_kl<<<kl_blocks, 256>>>(anchors);

    k_final<<<1, 1>>>(out);
}

// round 7
// speedup vs baseline: 1.7650x; 1.7650x over previous
#include <cuda_runtime.h>
#include <math.h>

#define BB 16
#define CC 384
#define HH 96
#define WW 96
#define HW (HH*WW)
#define CAND 2048
#define ANCH 512
#define KK2 49
#define TAU_INV 10.0f

// ---------------- scratch (device globals; no allocation anywhere) ----------------
__device__ float g_tn[(size_t)BB*HW*CC];      // teacher, normalized, channels-last [b][y][x][c]
__device__ float g_sn[(size_t)BB*HW*CC];      // student,  normalized, channels-last
__device__ float g_sims[(size_t)BB*CAND*KK2]; // teacher sims (already /TAU)
__device__ float g_ent[BB*CAND];
__device__ int   g_sel[BB*ANCH];
__device__ float g_loss;

// pixel offsets dy*WW+dx, row-major 7x7, padded to 52 with 0 (center: L1-resident)
__constant__ int c_doff[52] = {
 -291,-290,-289,-288,-287,-286,-285,
 -195,-194,-193,-192,-191,-190,-189,
  -99, -98, -97, -96, -95, -94, -93,
   -3,  -2,  -1,   0,   1,   2,   3,
   93,  94,  95,  96,  97,  98,  99,
  189, 190, 191, 192, 193, 194, 195,
  285, 286, 287, 288, 289, 290, 291,
    0,   0,   0 };

// ---------------- k0: zero the loss accumulator ----------------
__global__ void k_zero() { g_loss = 0.0f; }

// ---------------- k1: fused per-pixel L2-normalize + transpose to channels-last ----
#define PIX 16
template <int DST>
__global__ void __launch_bounds__(256) k_norm_transpose(const float* __restrict__ in) {
    __shared__ float tile[CC][PIX + 1];
    __shared__ float ssum[16][PIX];
    __shared__ float rinv[PIX];
    int blk  = blockIdx.x;
    int b    = blk / (HW / PIX);
    int pix0 = (blk % (HW / PIX)) * PIX;
    int t    = threadIdx.x;
    int p    = t & (PIX - 1);
    int cr   = t >> 4;                       // 0..15
    const float* src = in + (size_t)b * CC * HW + pix0;
    float acc = 0.0f;
#pragma unroll
    for (int i = 0; i < CC / 16; i++) {      // 24 iters
        int c = i * 16 + cr;
        float v = src[(size_t)c * HW + p];
        tile[c][p] = v;
        acc += v * v;
    }
    ssum[cr][p] = acc;
    __syncthreads();
    if (cr == 0) {
        float s = 0.0f;
#pragma unroll
        for (int r = 0; r < 16; r++) s += ssum[r][p];
        rinv[p] = 1.0f / fmaxf(sqrtf(s), 1e-12f);
    }
    __syncthreads();
    int lane = t & 31, w = t >> 5;           // 8 warps
    float* gout = (DST == 0) ? g_tn : g_sn;
    float* dst = gout + ((size_t)b * HW + pix0) * CC;
#pragma unroll
    for (int j = 0; j < PIX / 8; j++) {      // 2
        int pp = w * (PIX / 8) + j;
        float r = rinv[pp];
#pragma unroll
        for (int i2 = 0; i2 < CC / 32; i2++) {  // 12, coalesced 128B stores
            int c = lane + 32 * i2;
            dst[(size_t)pp * CC + c] = tile[c][pp] * r;
        }
    }
}

// ---------------- distributed window sims, MLP-friendly loop nest ----------------
// Warp layout: lane = 8*g + l. Group g owns offsets o = g*13+j. Lane l covers
// channels {l+8i} (float4). Channel-chunk loop OUTER, offset loop INNER:
// per iteration 13 independent LDG.128 feed 13 independent accumulators.
// Post: s[j] = sims(g*13+j)/TAU, identical across the 8 lanes of each group.
__device__ __forceinline__ void window_sims13(const float* __restrict__ feat,
                                              int b, int y, int x,
                                              int g, int l, float s[13]) {
    const float4* cp = ((const float4*)(feat + (size_t)b * HW * CC))
                     + (size_t)(y * WW + x) * (CC / 4);
    const float4* np[13];
#pragma unroll
    for (int j = 0; j < 13; j++)
        np[j] = cp + (ptrdiff_t)c_doff[g * 13 + j] * (CC / 4);
#pragma unroll
    for (int j = 0; j < 13; j++) s[j] = 0.0f;
#pragma unroll
    for (int i = 0; i < 12; i++) {
        int ci = l + 8 * i;
        float4 c = cp[ci];
        float4 n[13];
#pragma unroll
        for (int j = 0; j < 13; j++) n[j] = np[j][ci];   // 13 independent loads
#pragma unroll
        for (int j = 0; j < 13; j++) {
            s[j] = fmaf(c.x, n[j].x, s[j]);
            s[j] = fmaf(c.y, n[j].y, s[j]);
            s[j] = fmaf(c.z, n[j].z, s[j]);
            s[j] = fmaf(c.w, n[j].w, s[j]);
        }
    }
#pragma unroll
    for (int j = 0; j < 13; j++) {
        float v = s[j];
        v += __shfl_xor_sync(0xffffffffu, v, 1);
        v += __shfl_xor_sync(0xffffffffu, v, 2);
        v += __shfl_xor_sync(0xffffffffu, v, 4);
        s[j] = v * TAU_INV;
    }
}

// ---------------- k2: candidate sims (stored) + entropy ----------------
__global__ void __launch_bounds__(256, 2) k_cand(const int* __restrict__ anchors) {
    int gw   = (blockIdx.x * blockDim.x + threadIdx.x) >> 5;
    int lane = threadIdx.x & 31;
    if (gw >= BB * CAND) return;
    int b = gw >> 11;            // / CAND
    int m = gw & (CAND - 1);
    int y = anchors[2 * m], x = anchors[2 * m + 1];
    int g = lane >> 3, l = lane & 7;
    bool lead = (l == 0);

    float s[13];
    window_sims13(g_tn, b, y, x, g, l, s);

    // store sims row (group leaders: 4 lanes x 13 scattered floats)
    float* srow = g_sims + (size_t)gw * KK2;
    if (lead) {
#pragma unroll
        for (int j = 0; j < 13; j++) {
            int o = g * 13 + j;
            if (o < KK2) srow[o] = s[j];
        }
    }

    // distributed entropy of softmax(s)
    float mx = -1e30f;
#pragma unroll
    for (int j = 0; j < 13; j++) {
        int o = g * 13 + j;
        if (o < KK2) mx = fmaxf(mx, s[j]);
    }
#pragma unroll
    for (int off = 16; off; off >>= 1) mx = fmaxf(mx, __shfl_xor_sync(0xffffffffu, mx, off));

    float S = 0.0f;
#pragma unroll
    for (int j = 0; j < 13; j++) {
        int o = g * 13 + j;
        if (lead && o < KK2) S += __expf(s[j] - mx);
    }
#pragma unroll
    for (int off = 16; off; off >>= 1) S += __shfl_xor_sync(0xffffffffu, S, off);
    float rS = 1.0f / S;

    float tacc = 0.0f;
#pragma unroll
    for (int j = 0; j < 13; j++) {
        int o = g * 13 + j;
        if (lead && o < KK2) {
            float p = __expf(s[j] - mx) * rS;
            tacc += p * __logf(p + 1e-6f);
        }
    }
#pragma unroll
    for (int off = 16; off; off >>= 1) tacc += __shfl_xor_sync(0xffffffffu, tacc, off);

    if (lane == 0) g_ent[gw] = -tacc;
}

// ---------------- k3: exact top-512 (smallest entropy) per batch via bitonic sort --
__global__ void __launch_bounds__(1024) k_topk() {
    __shared__ float v[CAND];
    __shared__ int   idx[CAND];
    int b = blockIdx.x;
    int t = threadIdx.x;   // 1024
    v[t]          = g_ent[b * CAND + t];
    v[t + 1024]   = g_ent[b * CAND + t + 1024];
    idx[t]        = t;
    idx[t + 1024] = t + 1024;
    __syncthreads();
    for (int kk = 2; kk <= CAND; kk <<= 1) {
        for (int j = kk >> 1; j > 0; j >>= 1) {
            int i  = ((t & ~(j - 1)) << 1) | (t & (j - 1));
            int p2 = i | j;
            bool up = ((i & kk) == 0);
            float vi = v[i], vp = v[p2];
            if ((vi > vp) == up) {
                v[i] = vp; v[p2] = vi;
                int ti = idx[i]; idx[i] = idx[p2]; idx[p2] = ti;
            }
            __syncthreads();
        }
    }
    if (t < ANCH) g_sel[b * ANCH + t] = idx[t];   // ascending entropy -> smallest 512
}

// ---------------- k4: KL divergence over selected anchors ----------------
__global__ void __launch_bounds__(256, 2) k_kl(const int* __restrict__ anchors) {
    int gw   = (blockIdx.x * blockDim.x + threadIdx.x) >> 5;
    int lane = threadIdx.x & 31;
    if (gw >= BB * ANCH) return;
    int b = gw >> 9;             // / ANCH
    int m = g_sel[gw];
    int y = anchors[2 * m], x = anchors[2 * m + 1];
    int g = lane >> 3, l = lane & 7;
    bool lead = (l == 0);

    float ss[13];
    window_sims13(g_sn, b, y, x, g, l, ss);

    const float* trow = g_sims + (size_t)(b * CAND + m) * KK2;
    float st[13];
#pragma unroll
    for (int j = 0; j < 13; j++) {
        int o = g * 13 + j;
        st[j] = (o < KK2) ? trow[o] : -1e30f;   // group-broadcast loads
    }

    float mxs = -1e30f, mxt = -1e30f;
#pragma unroll
    for (int j = 0; j < 13; j++) {
        int o = g * 13 + j;
        if (o < KK2) mxs = fmaxf(mxs, ss[j]);
        mxt = fmaxf(mxt, st[j]);                // invalid slots are -1e30
    }
#pragma unroll
    for (int off = 16; off; off >>= 1) {
        mxs = fmaxf(mxs, __shfl_xor_sync(0xffffffffu, mxs, off));
        mxt = fmaxf(mxt, __shfl_xor_sync(0xffffffffu, mxt, off));
    }

    float Ss = 0.0f, St = 0.0f;
#pragma unroll
    for (int j = 0; j < 13; j++) {
        int o = g * 13 + j;
        if (lead && o < KK2) {
            Ss += __expf(ss[j] - mxs);
            St += __expf(st[j] - mxt);
        }
    }
#pragma unroll
    for (int off = 16; off; off >>= 1) {
        Ss += __shfl_xor_sync(0xffffffffu, Ss, off);
        St += __shfl_xor_sync(0xffffffffu, St, off);
    }
    float ls = __logf(Ss), lt = __logf(St);
    float rSt = 1.0f / St;

    float kacc = 0.0f;
#pragma unroll
    for (int j = 0; j < 13; j++) {
        int o = g * 13 + j;
        if (lead && o < KK2) {
            float dt = st[j] - mxt - lt;
            float ds = ss[j] - mxs - ls;
            kacc += __expf(st[j] - mxt) * (dt - ds);
        }
    }
#pragma unroll
    for (int off = 16; off; off >>= 1) kacc += __shfl_xor_sync(0xffffffffu, kacc, off);

    if (lane == 0) atomicAdd(&g_loss, kacc * rSt);
}

// ---------------- k5: finalize ----------------
__global__ void k_final(float* __restrict__ out) {
    out[0] = g_loss / (float)(BB * ANCH);
}

// ---------------- launch: kernel launches ONLY (graph-capture safe) ----------------
extern "C" void kernel_launch(void* const* d_in, const int* in_sizes, int n_in,
                              void* d_out, int out_size) {
    const float* student = (const float*)d_in[0];
    const float* teacher = (const float*)d_in[1];
    const int*   anchors = (const int*)d_in[2];
    float* out = (float*)d_out;

    k_zero<<<1, 1>>>();

    int nt_blocks = BB * HW / PIX;                  // 9216
    k_norm_transpose<0><<<nt_blocks, 256>>>(teacher);   // -> g_tn
    k_norm_transpose<1><<<nt_blocks, 256>>>(student);   // -> g_sn

    int cand_blocks = BB * CAND / 8;                // 4096 blocks, 8 warps each
    k_cand<<<cand_blocks, 256>>>(anchors);

    k_topk<<<BB, 1024>>>();

    int kl_blocks = BB * ANCH / 8;                  // 1024 blocks
    k_kl<<<kl_blocks, 256>>>(anchors);

    k_final<<<1, 1>>>(out);
}